// round 11
// baseline (speedup 1.0000x reference)
#include <cuda_runtime.h>
#include <cstdint>

// ============================================================================
// LSTM autoencoder  B=256 T=512 D=128 H=256
// Persistent-kernel design: 128 CTAs x 128 threads, 1 grid barrier per phase.
// ============================================================================

#define NB 128          // CTAs (one per SM, all resident)
#define NT 128          // threads per CTA
#define HB 65536        // 256*256 floats per h-state buffer

// ---- device-global scratch (no allocation allowed) -------------------------
__device__ float g_Wenc0[384 * 1024];   // [k][gatecol]  k<128: Wih(x), else Whh(h1)
__device__ float g_Wenc1[512 * 1024];   // k<256: Wih(h1), else Whh(h2)
__device__ float g_Wdec0[512 * 1024];   // k<256: W' = d_Wih0 @ fc_W (input=h2prev), else Whh(h1)
__device__ float g_Wdec1[512 * 1024];   // k<256: Wih(h1), else Whh(h2)
__device__ float g_benc0[1024];
__device__ float g_benc1[1024];
__device__ float g_bdec0[1024];         // bih+bhh + d_Wih0@fc_b   (t>=1)
__device__ float g_bdec0t0[1024];       // bih+bhh                 (t==0, zero input)
__device__ float g_bdec1[1024];
__device__ float g_fcWT[256 * 128];     // fc_W transposed: [u][d]

__device__ float g_h1e[2][HB];
__device__ float g_h2e[2][HB];
__device__ float g_h1d[2][HB];
__device__ float g_zero[HB];
__device__ float g_hist[512ll * HB];    // decoder h2 history [t][b][u]  (128 MB)

__device__ unsigned g_barCnt = 0;
__device__ unsigned g_barGen = 0;

// ---- helpers ---------------------------------------------------------------
__device__ __forceinline__ float sigf(float v) { return 1.0f / (1.0f + __expf(-v)); }

__device__ __forceinline__ void gridbar() {
    __syncthreads();
    if (threadIdx.x == 0) {
        unsigned gen = *(volatile unsigned*)&g_barGen;
        __threadfence();
        if (atomicAdd(&g_barCnt, 1u) == NB - 1) {
            atomicExch(&g_barCnt, 0u);
            __threadfence();
            atomicAdd(&g_barGen, 1u);
        } else {
            while (*(volatile unsigned*)&g_barGen == gen) { }
        }
        __threadfence();
    }
    __syncthreads();
}

#define CP16(dst_generic, src) do {                                         \
    unsigned _d = (unsigned)__cvta_generic_to_shared(dst_generic);          \
    asm volatile("cp.async.cg.shared.global [%0], [%1], 16;\n"              \
                 :: "r"(_d), "l"(src));                                     \
} while (0)

// smem layout (dynamic): As[2][32][68] then Bs[2][64][64]
#define AS_STRIDE 68
#define AS_BUF   2176       // 32*68
#define BS_BUF   4096       // 64*64
#define SMEM_FLOATS (2*AS_BUF + 2*BS_BUF)   // 12544 floats = 50176 B

// stage one 64-wide k tile of A (activations) and B (weights) into smem
__device__ __forceinline__ void stage_tile(
    int tile, int buf,
    const float* __restrict__ a0, long sa0, int k0len,
    const float* __restrict__ a1, long sa1,
    const float* __restrict__ W,
    float* As, float* Bs, int rb, int gb, int tid)
{
    int kbase = tile << 6;
    const float* sA; long st; int kl;
    if (kbase < k0len) { sA = a0; st = sa0; kl = kbase; }
    else               { sA = a1; st = sa1; kl = kbase - k0len; }
#pragma unroll
    for (int j = 0; j < 4; j++) {
        int idx = tid + j * NT;              // 0..511
        int r = idx >> 4, kq = idx & 15;
        const float* src = sA + (long)(rb * 32 + r) * st + kl + kq * 4;
        CP16(As + buf * AS_BUF + r * AS_STRIDE + kq * 4, src);
    }
#pragma unroll
    for (int j = 0; j < 8; j++) {
        int idx = tid + j * NT;              // 0..1023
        int kk = idx >> 4, gq = idx & 15;
        const float* src = W + (long)(kbase + kk) * 1024 + gb * 64 + gq * 4;
        CP16(Bs + buf * BS_BUF + kk * 64 + gq * 4, src);
    }
    asm volatile("cp.async.commit_group;\n");
}

// one LSTM cell phase: gates[256x1024] = A[256xK] @ W[Kx1024] + b ; nonlinearity
__device__ __forceinline__ void lstm_phase(
    const float* __restrict__ a0, long sa0, int k0len,
    const float* __restrict__ a1, long sa1,
    const float* __restrict__ W, const float* __restrict__ bias,
    int K, float* __restrict__ hout, float* c,
    float* As, float* Bs, int rb, int gb, int tx, int ty, int tid)
{
    float4 acc0 = {0.f,0.f,0.f,0.f}, acc1 = acc0, acc2 = acc1, acc3 = acc2;
    int nt = K >> 6;

    stage_tile(0, 0, a0, sa0, k0len, a1, sa1, W, As, Bs, rb, gb, tid);

    for (int tl = 0; tl < nt; tl++) {
        if (tl + 1 < nt) {
            stage_tile(tl + 1, (tl + 1) & 1, a0, sa0, k0len, a1, sa1, W, As, Bs, rb, gb, tid);
            asm volatile("cp.async.wait_group 1;\n");
        } else {
            asm volatile("cp.async.wait_group 0;\n");
        }
        __syncthreads();

        const float* Asb = As + (tl & 1) * AS_BUF + (ty * 4) * AS_STRIDE;
        const float* Bsb = Bs + (tl & 1) * BS_BUF + tx * 4;
#pragma unroll 4
        for (int k = 0; k < 64; k += 4) {
            float4 b0 = *(const float4*)(Bsb + (k + 0) * 64);
            float4 b1 = *(const float4*)(Bsb + (k + 1) * 64);
            float4 b2 = *(const float4*)(Bsb + (k + 2) * 64);
            float4 b3 = *(const float4*)(Bsb + (k + 3) * 64);
            float4 a;
#define FMAROW(ACC, RR)                                                      \
            a = *(const float4*)(Asb + (RR) * AS_STRIDE + k);                \
            ACC.x += a.x*b0.x + a.y*b1.x + a.z*b2.x + a.w*b3.x;              \
            ACC.y += a.x*b0.y + a.y*b1.y + a.z*b2.y + a.w*b3.y;              \
            ACC.z += a.x*b0.z + a.y*b1.z + a.z*b2.z + a.w*b3.z;              \
            ACC.w += a.x*b0.w + a.y*b1.w + a.z*b2.w + a.w*b3.w;
            FMAROW(acc0, 0)
            FMAROW(acc1, 1)
            FMAROW(acc2, 2)
            FMAROW(acc3, 3)
#undef FMAROW
        }
        __syncthreads();
    }

    // epilogue: 4 gates of one unit per acc, apply LSTM nonlinearity
    float4 bv = *(const float4*)&bias[gb * 64 + tx * 4];
    int col = gb * 16 + tx;
    float4 accs[4] = {acc0, acc1, acc2, acc3};
#pragma unroll
    for (int rr = 0; rr < 4; rr++) {
        float iv = accs[rr].x + bv.x;
        float fv = accs[rr].y + bv.y;
        float gv = accs[rr].z + bv.z;
        float ov = accs[rr].w + bv.w;
        float cn = sigf(fv) * c[rr] + sigf(iv) * tanhf(gv);
        c[rr] = cn;
        hout[(rb * 32 + ty * 4 + rr) * 256 + col] = sigf(ov) * tanhf(cn);
    }
}

// ---- persistent kernel ------------------------------------------------------
__global__ void __launch_bounds__(NT, 1) lstm_persistent(const float* __restrict__ x)
{
    extern __shared__ float sm[];
    float* As = sm;
    float* Bs = sm + 2 * AS_BUF;

    int tid = threadIdx.x, bid = blockIdx.x;
    int rb = bid & 7;        // row block  (8 x 32 rows)
    int gb = bid >> 3;       // gate block (16 x 64 gate cols)
    int tx = tid & 15;       // gate quad (unit)
    int ty = tid >> 4;       // row quad

    // zero-init state buffers
    for (int i = bid * NT + tid; i < HB; i += NB * NT) {
        g_h1e[0][i] = 0.f; g_h1e[1][i] = 0.f;
        g_h2e[0][i] = 0.f; g_h2e[1][i] = 0.f;
        g_h1d[0][i] = 0.f; g_h1d[1][i] = 0.f;
        g_zero[i]   = 0.f;
    }
    gridbar();

    float c1e[4] = {0.f,0.f,0.f,0.f};
    float c2e[4] = {0.f,0.f,0.f,0.f};

    // ---------------- encoder ----------------
    for (int t = 0; t < 512; t++) {
        int cur = t & 1, prv = cur ^ 1;
        lstm_phase(x + (long)t * 128, 65536L, 128, g_h1e[prv], 256L,
                   g_Wenc0, g_benc0, 384, g_h1e[cur], c1e,
                   As, Bs, rb, gb, tx, ty, tid);
        gridbar();
        lstm_phase(g_h1e[cur], 256L, 256, g_h2e[prv], 256L,
                   g_Wenc1, g_benc1, 512, g_h2e[cur], c2e,
                   As, Bs, rb, gb, tx, ty, tid);
        gridbar();
    }

    // decoder initial states = encoder final states (same thread->cell mapping)
    float c1d[4], c2d[4];
#pragma unroll
    for (int rr = 0; rr < 4; rr++) { c1d[rr] = c1e[rr]; c2d[rr] = c2e[rr]; }

    // ---------------- decoder ----------------
    for (int t = 0; t < 512; t++) {
        int cur = t & 1, prv = cur ^ 1;
        const float* in0 = (t == 0) ? g_zero    : (g_hist + (long)(t - 1) * HB);
        const float* h1p = (t == 0) ? g_h1e[1]  : g_h1d[prv];
        const float* h2p = (t == 0) ? g_h2e[1]  : (g_hist + (long)(t - 1) * HB);
        const float* b0  = (t == 0) ? g_bdec0t0 : g_bdec0;

        lstm_phase(in0, 256L, 256, h1p, 256L,
                   g_Wdec0, b0, 512, g_h1d[cur], c1d,
                   As, Bs, rb, gb, tx, ty, tid);
        gridbar();
        lstm_phase(g_h1d[cur], 256L, 256, h2p, 256L,
                   g_Wdec1, g_bdec1, 512, g_hist + (long)t * HB, c2d,
                   As, Bs, rb, gb, tx, ty, tid);
        gridbar();
    }
}

// ---- prep kernels -----------------------------------------------------------
// permute weights into [k][gatecol] with gatecol = 4*unit + gate  (gate: i,f,g,o)
__global__ void prep_std(const float* __restrict__ Wih, const float* __restrict__ Whh,
                         const float* __restrict__ bih, const float* __restrict__ bhh,
                         int inDim, int which)
{
    float* Wd = (which == 0) ? g_Wenc0 : (which == 1) ? g_Wenc1 : g_Wdec1;
    float* bd = (which == 0) ? g_benc0 : (which == 1) ? g_benc1 : g_bdec1;
    int K = inDim + 256;
    int idx = blockIdx.x * 256 + threadIdx.x;
    if (idx < K * 1024) {
        int k = idx >> 10, ccol = idx & 1023;
        int u = ccol >> 2, j = ccol & 3;
        int sr = j * 256 + u;
        Wd[idx] = (k < inDim) ? Wih[sr * inDim + k] : Whh[sr * 256 + (k - inDim)];
    }
    if (idx < 1024) {
        int u = idx >> 2, j = idx & 3;
        int sr = j * 256 + u;
        bd[idx] = bih[sr] + bhh[sr];
    }
}

// decoder layer 0: fold fc feedback:  W' = d_Wih0 @ fc_W,  b' += d_Wih0 @ fc_b
__global__ void prep_dec0(const float* __restrict__ Wih, const float* __restrict__ Whh,
                          const float* __restrict__ bih, const float* __restrict__ bhh,
                          const float* __restrict__ fcW, const float* __restrict__ fcb)
{
    int idx = blockIdx.x * 256 + threadIdx.x;
    if (idx < 512 * 1024) {
        int k = idx >> 10, ccol = idx & 1023;
        int u = ccol >> 2, j = ccol & 3;
        int sr = j * 256 + u;
        float v;
        if (k < 256) {
            float s = 0.f;
            for (int jj = 0; jj < 128; jj++)
                s += Wih[sr * 128 + jj] * fcW[jj * 256 + k];
            v = s;
        } else {
            v = Whh[sr * 256 + (k - 256)];
        }
        g_Wdec0[idx] = v;
    }
    if (idx < 1024) {
        int u = idx >> 2, j = idx & 3;
        int sr = j * 256 + u;
        float bb = bih[sr] + bhh[sr];
        g_bdec0t0[idx] = bb;
        float s = 0.f;
        for (int jj = 0; jj < 128; jj++)
            s += Wih[sr * 128 + jj] * fcb[jj];
        g_bdec0[idx] = bb + s;
    }
}

__global__ void prep_fcwt(const float* __restrict__ fcW)
{
    int idx = blockIdx.x * 256 + threadIdx.x;    // 32768
    if (idx < 256 * 128) {
        int u = idx >> 7, d = idx & 127;
        g_fcWT[idx] = fcW[d * 256 + u];
    }
}

// ---- final output GEMM:  y[b][t][:] = hist[t][b][:] @ fc_W^T + fc_b ---------
__global__ void __launch_bounds__(256) out_gemm(const float* __restrict__ fcb,
                                                float* __restrict__ out)
{
    __shared__ float As[32 * 64];
    __shared__ float Bs[64 * 128];
    int tid = threadIdx.x;
    long rowBase = (long)blockIdx.x * 32;   // global row g = t*256 + b
    int dx = tid & 31;   // d quad
    int ry = tid >> 5;   // 8 -> 4 rows each
    float acc[4][4] = {};
    for (int kb = 0; kb < 256; kb += 64) {
        __syncthreads();
#pragma unroll
        for (int j = 0; j < 2; j++) {
            int idx = tid + j * 256;  int r = idx >> 4, kq = idx & 15;
            *(float4*)&As[r * 64 + kq * 4] =
                *(const float4*)&g_hist[(rowBase + r) * 256 + kb + kq * 4];
        }
#pragma unroll
        for (int j = 0; j < 8; j++) {
            int idx = tid + j * 256;  int k = idx >> 5, dq = idx & 31;
            *(float4*)&Bs[k * 128 + dq * 4] =
                *(const float4*)&g_fcWT[(kb + k) * 128 + dq * 4];
        }
        __syncthreads();
#pragma unroll 4
        for (int k = 0; k < 64; k++) {
            float4 b = *(const float4*)&Bs[k * 128 + dx * 4];
#pragma unroll
            for (int rr = 0; rr < 4; rr++) {
                float a = As[(ry * 4 + rr) * 64 + k];
                acc[rr][0] += a * b.x; acc[rr][1] += a * b.y;
                acc[rr][2] += a * b.z; acc[rr][3] += a * b.w;
            }
        }
    }
    float4 bb = *(const float4*)&fcb[dx * 4];
#pragma unroll
    for (int rr = 0; rr < 4; rr++) {
        long g = rowBase + ry * 4 + rr;
        long b = g & 255, t = g >> 8;
        float4 v = make_float4(acc[rr][0] + bb.x, acc[rr][1] + bb.y,
                               acc[rr][2] + bb.z, acc[rr][3] + bb.w);
        *(float4*)&out[(b * 512 + t) * 128 + dx * 4] = v;
    }
}

// ---- launch -----------------------------------------------------------------
extern "C" void kernel_launch(void* const* d_in, const int* in_sizes, int n_in,
                              void* d_out, int out_size)
{
    const float* x      = (const float*)d_in[0];
    const float* eWih0  = (const float*)d_in[1];
    const float* eWhh0  = (const float*)d_in[2];
    const float* ebih0  = (const float*)d_in[3];
    const float* ebhh0  = (const float*)d_in[4];
    const float* eWih1  = (const float*)d_in[5];
    const float* eWhh1  = (const float*)d_in[6];
    const float* ebih1  = (const float*)d_in[7];
    const float* ebhh1  = (const float*)d_in[8];
    const float* dWih0  = (const float*)d_in[9];
    const float* dWhh0  = (const float*)d_in[10];
    const float* dbih0  = (const float*)d_in[11];
    const float* dbhh0  = (const float*)d_in[12];
    const float* dWih1  = (const float*)d_in[13];
    const float* dWhh1  = (const float*)d_in[14];
    const float* dbih1  = (const float*)d_in[15];
    const float* dbhh1  = (const float*)d_in[16];
    const float* fcW    = (const float*)d_in[17];
    const float* fcb    = (const float*)d_in[18];
    float* out = (float*)d_out;

    prep_std<<<1536, 256>>>(eWih0, eWhh0, ebih0, ebhh0, 128, 0);
    prep_std<<<2048, 256>>>(eWih1, eWhh1, ebih1, ebhh1, 256, 1);
    prep_std<<<2048, 256>>>(dWih1, dWhh1, dbih1, dbhh1, 256, 2);
    prep_dec0<<<2048, 256>>>(dWih0, dWhh0, dbih0, dbhh0, fcW, fcb);
    prep_fcwt<<<128, 256>>>(fcW);

    cudaFuncSetAttribute(lstm_persistent,
                         cudaFuncAttributeMaxDynamicSharedMemorySize,
                         SMEM_FLOATS * 4);
    lstm_persistent<<<NB, NT, SMEM_FLOATS * 4>>>(x);

    out_gemm<<<4096, 256>>>(fcb, out);
}